// round 2
// baseline (speedup 1.0000x reference)
#include <cuda_runtime.h>
#include <cuda_bf16.h>
#include <cstdint>

// ---------------------------------------------------------------------------
// Problem constants
// ---------------------------------------------------------------------------
#define BB 16
#define TT 1024
#define FIN 128
#define HH 256
#define G4 1024            // 4*H
#define MM (BB*TT)         // 16384

// ---------------------------------------------------------------------------
// Scratch (static device arrays; no dynamic allocation allowed)
// ---------------------------------------------------------------------------
__device__ float g_xg [MM * G4];      // gate preactivations (reused layer0/1)
__device__ float g_h1 [MM * HH];      // layer0 hidden sequence
__device__ float g_h2 [MM * HH];      // layer1 hidden sequence (lstm_out)
__device__ float g_Q  [MM * HH];
__device__ float g_K  [MM * HH];
__device__ float g_V  [MM * HH];
__device__ float g_S  [BB * TT * TT]; // attention scores / probs
__device__ float g_att[MM * HH];
__device__ float g_dump[4 * BB * HH]; // fallback sink for h_n/c_n

// ---------------------------------------------------------------------------
// Helpers
// ---------------------------------------------------------------------------
__device__ __forceinline__ uint32_t smem_u32(const void* p) {
    return (uint32_t)__cvta_generic_to_shared(p);
}
__device__ __forceinline__ void st_cluster_f32(uint32_t saddr, int dst_rank, float v) {
    uint32_t r;
    asm volatile("mapa.shared::cluster.u32 %0, %1, %2;" : "=r"(r) : "r"(saddr), "r"(dst_rank));
    asm volatile("st.shared::cluster.f32 [%0], %1;" :: "r"(r), "f"(v) : "memory");
}
__device__ __forceinline__ void cluster_sync_all() {
    asm volatile("barrier.cluster.arrive.aligned;" ::: "memory");
    asm volatile("barrier.cluster.wait.aligned;" ::: "memory");
}
__device__ __forceinline__ float fast_sigmoid(float x) {
    return 1.f / (1.f + __expf(-x));
}
__device__ __forceinline__ float fast_tanh(float x) {
    x = fminf(fmaxf(x, -15.f), 15.f);
    float e = __expf(2.f * x);
    return (e - 1.f) / (e + 1.f);
}

// ---------------------------------------------------------------------------
// Persistent LSTM recurrence kernel.
// Grid: 128 CTAs = 16 clusters(=batches) x 8 ranks. 256 threads/CTA.
// Each CTA owns hidden dims [32*rank, 32*rank+32) and keeps its Whh slice
// (4 gates x 32 hid x 256 in = 128KB) in registers (float4 wreg[32] / thread).
// Thread t: u = t>>3 selects 4 outputs o=4u..4u+3, kc = t&7 selects the
// k-subset {kc + 8j}. 8-lane shfl reduction completes each dot product.
// h broadcast to all 8 cluster CTAs via DSMEM, double-buffered, one
// cluster.sync per timestep.
// ---------------------------------------------------------------------------
__global__ void __cluster_dims__(8, 1, 1) __launch_bounds__(256, 1)
lstm_rec_kernel(const float* __restrict__ xg, const float* __restrict__ Whh,
                float* __restrict__ hseq, float* __restrict__ hn, float* __restrict__ cn)
{
    __shared__ float h_all[2][HH];
    __shared__ float gates_s[128];

    const int tid   = threadIdx.x;
    const int rank  = blockIdx.x & 7;
    const int batch = blockIdx.x >> 3;
    const int u     = tid >> 3;   // 0..31 : output group (4 outputs)
    const int kc    = tid & 7;    // 0..7  : k-subset

    // ---- load Whh slice into registers ----
    float4 wreg[32];
    const int o0  = 4 * u;
    #pragma unroll
    for (int j = 0; j < 32; j++) {
        int k = kc + 8 * j;
        float w0, w1, w2, w3;
        {
            int o = o0 + 0; int row = ((o >> 5) << 8) + 32 * rank + (o & 31);
            w0 = Whh[row * HH + k];
        }
        {
            int o = o0 + 1; int row = ((o >> 5) << 8) + 32 * rank + (o & 31);
            w1 = Whh[row * HH + k];
        }
        {
            int o = o0 + 2; int row = ((o >> 5) << 8) + 32 * rank + (o & 31);
            w2 = Whh[row * HH + k];
        }
        {
            int o = o0 + 3; int row = ((o >> 5) << 8) + 32 * rank + (o & 31);
            w3 = Whh[row * HH + k];
        }
        wreg[j] = make_float4(w0, w1, w2, w3);
    }

    h_all[0][tid] = 0.f;  // 256 threads cover all 256 entries of buffer 0

    float c_state = 0.f;
    uint32_t haddr[2] = {0, 0};
    if (tid < 32) {
        haddr[0] = smem_u32(&h_all[0][32 * rank + tid]);
        haddr[1] = smem_u32(&h_all[1][32 * rank + tid]);
    }
    __syncthreads();
    cluster_sync_all();

    const long xg_base = (long)batch * TT * G4;
    const int  xg_col  = ((o0 >> 5) << 8) + 32 * rank + (o0 & 31); // 4 consecutive cols

    for (int t = 0; t < TT; t++) {
        const int rb = t & 1;       // read buffer
        const int wb = rb ^ 1;      // write buffer

        // prefetch gate preactivation (hidden under the GEMV)
        float4 xgv = make_float4(0.f, 0.f, 0.f, 0.f);
        if (kc == 0) {
            xgv = *(const float4*)(xg + xg_base + (long)t * G4 + xg_col);
        }

        // GEMV: acc_c = sum_{k in subset} Whh[o][k] * h[k]
        float4 acc = make_float4(0.f, 0.f, 0.f, 0.f);
        const float* hrow = h_all[rb];
        #pragma unroll
        for (int j = 0; j < 32; j++) {
            float h = hrow[kc + 8 * j];
            acc.x = fmaf(wreg[j].x, h, acc.x);
            acc.y = fmaf(wreg[j].y, h, acc.y);
            acc.z = fmaf(wreg[j].z, h, acc.z);
            acc.w = fmaf(wreg[j].w, h, acc.w);
        }
        // reduce over the 8 lanes sharing u (lanes grouped: kc = lane&7)
        #pragma unroll
        for (int off = 4; off >= 1; off >>= 1) {
            acc.x += __shfl_xor_sync(0xffffffffu, acc.x, off);
            acc.y += __shfl_xor_sync(0xffffffffu, acc.y, off);
            acc.z += __shfl_xor_sync(0xffffffffu, acc.z, off);
            acc.w += __shfl_xor_sync(0xffffffffu, acc.w, off);
        }
        if (kc == 0) {
            *(float4*)&gates_s[o0] =
                make_float4(acc.x + xgv.x, acc.y + xgv.y, acc.z + xgv.z, acc.w + xgv.w);
        }
        __syncthreads();

        if (tid < 32) {
            const int hid = tid;
            float gi = gates_s[hid];
            float gf = gates_s[32 + hid];
            float gg = gates_s[64 + hid];
            float go = gates_s[96 + hid];
            float ig = fast_sigmoid(gi);
            float fg = fast_sigmoid(gf);
            float gt = fast_tanh(gg);
            float og = fast_sigmoid(go);
            c_state = fg * c_state + ig * gt;
            float h = og * fast_tanh(c_state);
            hseq[((long)batch * TT + t) * HH + 32 * rank + hid] = h;
            uint32_t dst = haddr[wb];
            #pragma unroll
            for (int d = 0; d < 8; d++) st_cluster_f32(dst, d, h);
            if (t == TT - 1) {
                hn[batch * HH + 32 * rank + hid] = h;
                cn[batch * HH + 32 * rank + hid] = c_state;
            }
        }
        cluster_sync_all();
    }
}

// ---------------------------------------------------------------------------
// SGEMM: C[M,N] = A[M,K] @ B^T (b_nt=1, B is [N,K]) or A @ B (b_nt=0, B is [K,N])
// + optional bias1[n] + bias2[n] + residual[m,n]. Batched via gridDim.z with
// element strides sA/sB/sC. Tiles 128x128x8, 256 threads, 8x8 microtiles.
// All dims assumed divisible (true for this problem).
// ---------------------------------------------------------------------------
__global__ __launch_bounds__(256) void sgemm_kernel(
    const float* __restrict__ A, const float* __restrict__ B, float* __restrict__ C,
    int M, int N, int K,
    long sA, long sB, long sC,
    const float* __restrict__ bias1, const float* __restrict__ bias2,
    const float* __restrict__ res,
    int b_nt)
{
    __shared__ float As[8][132];
    __shared__ float Bs[8][132];

    const int bz = blockIdx.z;
    A += (long)bz * sA;
    B += (long)bz * sB;
    C += (long)bz * sC;

    const int bm = blockIdx.y * 128;
    const int bn = blockIdx.x * 128;
    const int tid = threadIdx.x;
    const int tx = tid & 15;
    const int ty = tid >> 4;

    float acc[8][8];
    #pragma unroll
    for (int i = 0; i < 8; i++)
        #pragma unroll
        for (int j = 0; j < 8; j++) acc[i][j] = 0.f;

    const int lr  = tid >> 1;        // 0..127
    const int lc4 = (tid & 1) * 4;   // 0 or 4
    const int kb  = tid >> 5;        // 0..7   (NN B load)
    const int nb  = (tid & 31) * 4;  // 0..124

    for (int k0 = 0; k0 < K; k0 += 8) {
        float4 a4 = *(const float4*)(A + (long)(bm + lr) * K + k0 + lc4);
        As[lc4 + 0][lr] = a4.x;
        As[lc4 + 1][lr] = a4.y;
        As[lc4 + 2][lr] = a4.z;
        As[lc4 + 3][lr] = a4.w;
        if (b_nt) {
            float4 b4 = *(const float4*)(B + (long)(bn + lr) * K + k0 + lc4);
            Bs[lc4 + 0][lr] = b4.x;
            Bs[lc4 + 1][lr] = b4.y;
            Bs[lc4 + 2][lr] = b4.z;
            Bs[lc4 + 3][lr] = b4.w;
        } else {
            float4 b4 = *(const float4*)(B + (long)(k0 + kb) * N + bn + nb);
            *(float4*)&Bs[kb][nb] = b4;
        }
        __syncthreads();

        #pragma unroll
        for (int kk = 0; kk < 8; kk++) {
            float a[8], b[8];
            *(float4*)&a[0] = *(const float4*)&As[kk][ty * 4];
            *(float4*)&a[4] = *(const float4*)&As[kk][64 + ty * 4];
            *(float4*)&b[0] = *(const float4*)&Bs[kk][tx * 4];
            *(float4*)&b[4] = *(const float4*)&Bs[kk][64 + tx * 4];
            #pragma unroll
            for (int i = 0; i < 8; i++)
                #pragma unroll
                for (int j = 0; j < 8; j++)
                    acc[i][j] = fmaf(a[i], b[j], acc[i][j]);
        }
        __syncthreads();
    }

    // epilogue
    #pragma unroll
    for (int ih = 0; ih < 2; ih++) {
        #pragma unroll
        for (int i = 0; i < 4; i++) {
            int m = bm + ih * 64 + ty * 4 + i;
            #pragma unroll
            for (int jh = 0; jh < 2; jh++) {
                int n = bn + jh * 64 + tx * 4;
                float4 v;
                v.x = acc[ih * 4 + i][jh * 4 + 0];
                v.y = acc[ih * 4 + i][jh * 4 + 1];
                v.z = acc[ih * 4 + i][jh * 4 + 2];
                v.w = acc[ih * 4 + i][jh * 4 + 3];
                if (bias1) {
                    const float4 b1 = *(const float4*)(bias1 + n);
                    v.x += b1.x; v.y += b1.y; v.z += b1.z; v.w += b1.w;
                }
                if (bias2) {
                    const float4 b2 = *(const float4*)(bias2 + n);
                    v.x += b2.x; v.y += b2.y; v.z += b2.z; v.w += b2.w;
                }
                if (res) {
                    const float4 r = *(const float4*)(res + (long)m * N + n);
                    v.x += r.x; v.y += r.y; v.z += r.z; v.w += r.w;
                }
                *(float4*)(C + (long)m * N + n) = v;
            }
        }
    }
}

// ---------------------------------------------------------------------------
// Softmax with ARMA modulation. One block (256 thr) per (b,q) row of 1024.
// mod depends only on d=|q-k| and is non-trivial only for d<=3.
// ---------------------------------------------------------------------------
__global__ __launch_bounds__(256) void softmax_mod_kernel(
    float* __restrict__ S, const float* __restrict__ ar_w, const float* __restrict__ ma_w)
{
    __shared__ float red[8];
    const int row = blockIdx.x;          // b*1024 + q
    const int q = row & (TT - 1);
    float* Sr = S + (long)row * TT;

    const float m0 = ma_w[0], m1 = ma_w[1];
    const float a0 = ar_w[0], a1 = ar_w[1], a2 = ar_w[2];
    const float mod0 = __expf(m0 + m1);
    const float mod1 = __expf(a0 + m0 + m1);
    const float mod2 = __expf(a1 + m1);
    const float mod3 = __expf(a2);

    const int t = threadIdx.x;
    float v[4];
    float mx = -1e30f;
    #pragma unroll
    for (int i = 0; i < 4; i++) {
        int k = t + 256 * i;
        float s = Sr[k] * 0.0625f;   // 1/sqrt(256)
        int d = ::abs(q - k);
        float md = (d > 3) ? 1.f : (d == 0 ? mod0 : (d == 1 ? mod1 : (d == 2 ? mod2 : mod3)));
        v[i] = s * md;
        mx = fmaxf(mx, v[i]);
    }
    #pragma unroll
    for (int off = 16; off; off >>= 1) mx = fmaxf(mx, __shfl_xor_sync(~0u, mx, off));
    if ((t & 31) == 0) red[t >> 5] = mx;
    __syncthreads();
    mx = red[0];
    #pragma unroll
    for (int w = 1; w < 8; w++) mx = fmaxf(mx, red[w]);

    float sum = 0.f;
    #pragma unroll
    for (int i = 0; i < 4; i++) { v[i] = __expf(v[i] - mx); sum += v[i]; }
    #pragma unroll
    for (int off = 16; off; off >>= 1) sum += __shfl_xor_sync(~0u, sum, off);
    __syncthreads();
    if ((t & 31) == 0) red[t >> 5] = sum;
    __syncthreads();
    sum = 0.f;
    #pragma unroll
    for (int w = 0; w < 8; w++) sum += red[w];
    const float inv = 1.f / sum;
    #pragma unroll
    for (int i = 0; i < 4; i++) Sr[t + 256 * i] = v[i] * inv;
}

// ---------------------------------------------------------------------------
// Launch
// ---------------------------------------------------------------------------
extern "C" void kernel_launch(void* const* d_in, const int* in_sizes, int n_in,
                              void* d_out, int out_size)
{
    const float* x    = (const float*)d_in[0];
    const float* Wih0 = (const float*)d_in[1];
    const float* Whh0 = (const float*)d_in[2];
    const float* bih0 = (const float*)d_in[3];
    const float* bhh0 = (const float*)d_in[4];
    const float* Wih1 = (const float*)d_in[5];
    const float* Whh1 = (const float*)d_in[6];
    const float* bih1 = (const float*)d_in[7];
    const float* bhh1 = (const float*)d_in[8];
    const float* ar_w = (const float*)d_in[9];
    const float* ma_w = (const float*)d_in[10];
    const float* Wq   = (const float*)d_in[11];
    const float* bq   = (const float*)d_in[12];
    const float* Wk   = (const float*)d_in[13];
    const float* bk   = (const float*)d_in[14];
    const float* Wv   = (const float*)d_in[15];
    const float* bv   = (const float*)d_in[16];
    const float* Wo   = (const float*)d_in[17];
    const float* bo   = (const float*)d_in[18];

    float* out = (float*)d_out;

    float *xg, *h1, *h2, *Q, *K, *V, *S, *att, *dump;
    cudaGetSymbolAddress((void**)&xg,  g_xg);
    cudaGetSymbolAddress((void**)&h1,  g_h1);
    cudaGetSymbolAddress((void**)&h2,  g_h2);
    cudaGetSymbolAddress((void**)&Q,   g_Q);
    cudaGetSymbolAddress((void**)&K,   g_K);
    cudaGetSymbolAddress((void**)&V,   g_V);
    cudaGetSymbolAddress((void**)&S,   g_S);
    cudaGetSymbolAddress((void**)&att, g_att);
    cudaGetSymbolAddress((void**)&dump, g_dump);

    // h_n / c_n destinations (appended after `out` if the buffer has room)
    const int OUT_ELEMS = MM * HH;            // 4194304
    float* hn_base;
    float* cn_base;
    if (out_size >= OUT_ELEMS + 4 * BB * HH) {
        hn_base = out + OUT_ELEMS;
        cn_base = out + OUT_ELEMS + 2 * BB * HH;
    } else {
        hn_base = dump;
        cn_base = dump + BB * HH;
    }

    const dim3 g_xg_grid(G4 / 128, MM / 128, 1);
    const dim3 g_qkv(HH / 128, MM / 128, 1);
    const dim3 g_sc(TT / 128, TT / 128, BB);
    const dim3 g_av(HH / 128, TT / 128, BB);

    // layer 0
    sgemm_kernel<<<g_xg_grid, 256>>>(x, Wih0, xg, MM, G4, FIN, 0, 0, 0, bih0, bhh0, nullptr, 1);
    lstm_rec_kernel<<<128, 256>>>(xg, Whh0, h1, hn_base, cn_base);
    // layer 1
    sgemm_kernel<<<g_xg_grid, 256>>>(h1, Wih1, xg, MM, G4, HH, 0, 0, 0, bih1, bhh1, nullptr, 1);
    lstm_rec_kernel<<<128, 256>>>(xg, Whh1, h2, hn_base + BB * HH, cn_base + BB * HH);
    // Q, K, V
    sgemm_kernel<<<g_qkv, 256>>>(h2, Wq, Q, MM, HH, HH, 0, 0, 0, bq, nullptr, nullptr, 1);
    sgemm_kernel<<<g_qkv, 256>>>(h2, Wk, K, MM, HH, HH, 0, 0, 0, bk, nullptr, nullptr, 1);
    sgemm_kernel<<<g_qkv, 256>>>(h2, Wv, V, MM, HH, HH, 0, 0, 0, bv, nullptr, nullptr, 1);
    // scores = Q @ K^T (batched)
    sgemm_kernel<<<g_sc, 256>>>(Q, K, S, TT, TT, HH,
                                (long)TT * HH, (long)TT * HH, (long)TT * TT,
                                nullptr, nullptr, nullptr, 1);
    // softmax(scores/sqrt(H) * mod)
    softmax_mod_kernel<<<BB * TT, 256>>>(S, ar_w, ma_w);
    // attended = attn @ V (batched, NN)
    sgemm_kernel<<<g_av, 256>>>(S, V, att, TT, HH, TT,
                                (long)TT * TT, (long)TT * HH, (long)TT * HH,
                                nullptr, nullptr, nullptr, 0);
    // out = attended @ Wo^T + bo + lstm_out
    sgemm_kernel<<<g_qkv, 256>>>(att, Wo, out, MM, HH, HH, 0, 0, 0, bo, nullptr, h2, 1);
}